// round 8
// baseline (speedup 1.0000x reference)
#include <cuda_runtime.h>
#include <cuda_bf16.h>
#include <cstdint>

// Problem constants (PairInitOPM: B=1, L=768, sd=384, pd=128)
#define Lq 768
#define SD 384
#define PD 128
#define SD4 (SD / 4)   // 96 float4 per s row
#define PD4 (PD / 4)   // 32 float4 per wm half-row

// Scratch (allocation-free rule: __device__ globals)
__device__ float g_P[Lq * PD];  // si  (includes bi)
__device__ float g_Q[Lq * PD];  // sj  (includes bj)
__device__ float g_U[Lq * PD];  // zi + bm
__device__ float g_V[Lq * PD];  // zj

// ---- cp.async helpers ----
__device__ __forceinline__ void cp_async16(uint32_t dst_smem, const void* src) {
    asm volatile("cp.async.cg.shared.global [%0], [%1], 16;" :: "r"(dst_smem), "l"(src));
}
__device__ __forceinline__ void cp_commit() { asm volatile("cp.async.commit_group;"); }
template <int N>
__device__ __forceinline__ void cp_wait() { asm volatile("cp.async.wait_group %0;" :: "n"(N)); }

// ---------------------------------------------------------------------------
// Kernel 1: 128 blocks x 512 threads (one wave), TI=6 rows/block.
// SPLIT-K: threads [0,256) take the low K half, [256,512) the high half;
// each half runs its own cp.async double-buffered weight-tile pipeline
// (KT=16 scalars = 4 float4). Cross-half reduction via smem at phase ends.
// 4 warps/SMSP (vs 2 before) -> latency chains overlap.
// SMEM: w[2 halves][2 bufs][256*WPAD f4] (82KB) + s (9.2KB) + sisj (6KB) = 97KB.
// ---------------------------------------------------------------------------
#define TI 6
#define WPAD 5                      // f4 per col slot (4 data + 1 pad; odd -> conflict-free)
#define WBUF (256 * WPAD)           // f4 per buffer
#define NT_A 12                     // tiles per half, phase A (12*4 = 48 f4 = SD4/2)
#define NT_B 4                      // tiles per half, phase B (4*4 = 16 f4 = PD4/2)
#define K1_SMEM_BYTES ((4 * WBUF + TI * SD4 + TI * 64) * 16)

__global__ __launch_bounds__(512) void k1_proj(
    const float* __restrict__ s,
    const float* __restrict__ wi, const float* __restrict__ bi,
    const float* __restrict__ wj, const float* __restrict__ bj,
    const float* __restrict__ wm, const float* __restrict__ bm)
{
    extern __shared__ float4 sm4[];
    float4* w_sh4 = sm4;                       // [4][WBUF]  (half*2 + buf)
    float4* s_sh4 = sm4 + 4 * WBUF;            // [TI][SD4]; red overlays later
    float4* sisj4 = s_sh4 + TI * SD4;          // [TI][64]

    const int t   = threadIdx.x;
    const int h   = t >> 8;                    // k-half (0/1)
    const int tl  = t & 255;                   // output column c = tl
    const int i0  = blockIdx.x * TI;
    const uint32_t w_sm = (uint32_t)__cvta_generic_to_shared(w_sh4);

    // Staging role: 4 consecutive threads cover one row's 4 f4 (64B coalesced)
    const int sc  = tl >> 2;                   // base col (0..63), step 64
    const int sm_ = tl & 3;                    // f4 index within tile

    // Load s rows (float4, coalesced; 512 threads)
    const float4* __restrict__ S4 = (const float4*)s;
    for (int idx = t; idx < TI * SD4; idx += 512)
        s_sh4[idx] = S4[i0 * SD4 + idx];

    float acc[TI];
#pragma unroll
    for (int r = 0; r < TI; r++) acc[r] = 0.f;

    // ---------------- Phase A ----------------
    auto stageA = [&](int tile, int b) {
        const int kq0 = h * 48 + tile * 4;
#pragma unroll
        for (int it = 0; it < 4; it++) {
            int c = sc + 64 * it;
            const float* wr = (c < PD) ? (wi + c * SD) : (wj + (c - PD) * SD);
            cp_async16(w_sm + (uint32_t)(((h * 2 + b) * WBUF + c * WPAD + sm_) * 16),
                       (const float4*)wr + kq0 + sm_);
        }
        cp_commit();
    };

    stageA(0, 0);
    for (int tile = 0; tile < NT_A; tile++) {
        if (tile + 1 < NT_A) { stageA(tile + 1, (tile + 1) & 1); cp_wait<1>(); }
        else                 { cp_wait<0>(); }
        __syncthreads();                        // tile visible (covers s on t0)
        const float4* wb = w_sh4 + (h * 2 + (tile & 1)) * WBUF;
        const int kq0 = h * 48 + tile * 4;
#pragma unroll
        for (int m = 0; m < 4; m++) {
            float4 w4 = wb[tl * WPAD + m];      // conflict-free LDS.128
#pragma unroll
            for (int r = 0; r < TI; r++) {
                float4 s4 = s_sh4[r * SD4 + kq0 + m];   // broadcast
                acc[r] = fmaf(s4.x, w4.x, acc[r]);
                acc[r] = fmaf(s4.y, w4.y, acc[r]);
                acc[r] = fmaf(s4.z, w4.z, acc[r]);
                acc[r] = fmaf(s4.w, w4.w, acc[r]);
            }
        }
        __syncthreads();                        // buffer reusable
    }

    // ---- cross-half reduction A (red overlays dead s_sh region) ----
    float* red  = (float*)s_sh4;                // [TI][256]
    float* sisj = (float*)sisj4;                // [TI][256]
    if (h == 1) {
#pragma unroll
        for (int r = 0; r < TI; r++) red[r * 256 + tl] = acc[r];
    }
    __syncthreads();
    if (h == 0) {
        float b = (tl < PD) ? bi[tl] : bj[tl - PD];
#pragma unroll
        for (int r = 0; r < TI; r++) {
            acc[r] += red[r * 256 + tl] + b;    // full si/sj value
            sisj[r * 256 + tl] = acc[r];
        }
    }

    // ---------------- Phase B ----------------
    const int which = tl >> 7;                  // 0 -> zi input si, 1 -> zj input sj
    const int e     = tl & 127;
    float az[TI];
#pragma unroll
    for (int r = 0; r < TI; r++) az[r] = 0.f;

    auto stageB = [&](int tile, int b) {
        const int kq0 = h * 16 + tile * 4;      // f4 index within half-row [0,32)
#pragma unroll
        for (int it = 0; it < 4; it++) {
            int c = sc + 64 * it;
            const float4* wr4 = (const float4*)wm + (c & 127) * 64 + (c >> 7) * 32;
            cp_async16(w_sm + (uint32_t)(((h * 2 + b) * WBUF + c * WPAD + sm_) * 16),
                       wr4 + kq0 + sm_);
        }
        cp_commit();
    };

    stageB(0, 0);
    __syncthreads();                            // sisj published before reads
    for (int tile = 0; tile < NT_B; tile++) {
        if (tile + 1 < NT_B) { stageB(tile + 1, (tile + 1) & 1); cp_wait<1>(); }
        else                 { cp_wait<0>(); }
        __syncthreads();                        // tile visible
        const float4* wb = w_sh4 + (h * 2 + (tile & 1)) * WBUF;
        const int kq0 = h * 16 + tile * 4;
#pragma unroll
        for (int m = 0; m < 4; m++) {
            float4 w4 = wb[tl * WPAD + m];
#pragma unroll
            for (int r = 0; r < TI; r++) {
                float4 z4 = sisj4[r * 64 + which * 32 + kq0 + m];  // broadcast
                az[r] = fmaf(z4.x, w4.x, az[r]);
                az[r] = fmaf(z4.y, w4.y, az[r]);
                az[r] = fmaf(z4.z, w4.z, az[r]);
                az[r] = fmaf(z4.w, w4.w, az[r]);
            }
        }
        __syncthreads();
    }

    // ---- cross-half reduction B + outputs (half 0 writes) ----
    if (h == 1) {
#pragma unroll
        for (int r = 0; r < TI; r++) red[r * 256 + tl] = az[r];
    }
    __syncthreads();
    if (h == 0) {
        const float bmv = bm[e];
#pragma unroll
        for (int r = 0; r < TI; r++) {
            float z = az[r] + red[r * 256 + tl];
            int i = i0 + r;
            if (which == 0) {
                g_P[i * PD + e] = acc[r];
                g_U[i * PD + e] = z + bmv;
            } else {
                g_Q[i * PD + e] = acc[r];
                g_V[i * PD + e] = z;
            }
        }
    }
}

// ---------------------------------------------------------------------------
// Kernel 2: z0[i,j,d] = U[i,d] + V[j,d] + P[i,d]*Q[j,d]
// EXACT R3 config (measured 47.3-48.2us @ ~64% DRAM across 4 rounds).
// ---------------------------------------------------------------------------
#define BI 8
#define BJ 32

__global__ __launch_bounds__(256) void k2_outer(float* __restrict__ out)
{
    __shared__ float4 q_sh[BJ * 32];   // 16 KB
    __shared__ float4 v_sh[BJ * 32];   // 16 KB

    const int t  = threadIdx.x;
    const int tx = t & 31;             // d quad: d = 4*tx
    const int ty = t >> 5;             // i within tile (0..7)
    const int i  = blockIdx.x * BI + ty;
    const int j0 = blockIdx.y * BJ;

    const float4* __restrict__ P4 = (const float4*)g_P;
    const float4* __restrict__ Q4 = (const float4*)g_Q;
    const float4* __restrict__ U4 = (const float4*)g_U;
    const float4* __restrict__ V4 = (const float4*)g_V;

#pragma unroll
    for (int m = 0; m < (BJ * 32) / 256; m++) {
        int idx = t + m * 256;
        q_sh[idx] = Q4[j0 * 32 + idx];
        v_sh[idx] = V4[j0 * 32 + idx];
    }

    const float4 p = P4[i * 32 + tx];
    const float4 u = U4[i * 32 + tx];
    __syncthreads();

    float4* out4 = (float4*)out;
    size_t base = ((size_t)i * Lq + j0) * 32 + tx;

#pragma unroll 8
    for (int jj = 0; jj < BJ; jj++) {
        float4 q = q_sh[jj * 32 + tx];     // LDS.128, conflict-free
        float4 v = v_sh[jj * 32 + tx];
        float4 o;
        o.x = fmaf(p.x, q.x, u.x + v.x);
        o.y = fmaf(p.y, q.y, u.y + v.y);
        o.z = fmaf(p.z, q.z, u.z + v.z);
        o.w = fmaf(p.w, q.w, u.w + v.w);
        __stcs(&out4[base + (size_t)jj * 32], o);  // streaming store
    }
}

// ---------------------------------------------------------------------------
extern "C" void kernel_launch(void* const* d_in, const int* in_sizes, int n_in,
                              void* d_out, int out_size)
{
    const float* s  = (const float*)d_in[0];
    const float* wi = (const float*)d_in[1];
    const float* bi = (const float*)d_in[2];
    const float* wj = (const float*)d_in[3];
    const float* bj = (const float*)d_in[4];
    const float* wm = (const float*)d_in[5];
    const float* bm = (const float*)d_in[6];
    float* out = (float*)d_out;

    // Idempotent, deterministic, not an allocation: raise dynamic-smem cap.
    cudaFuncSetAttribute(k1_proj, cudaFuncAttributeMaxDynamicSharedMemorySize,
                         K1_SMEM_BYTES);

    k1_proj<<<Lq / TI, 512, K1_SMEM_BYTES>>>(s, wi, bi, wj, bj, wm, bm);

    dim3 grid2(Lq / BI, Lq / BJ);
    k2_outer<<<grid2, 256>>>(out);
}